// round 16
// baseline (speedup 1.0000x reference)
#include <cuda_runtime.h>
#include <cuda_bf16.h>
#include <cstdint>

// ThoughtEngine: B=8, L=1024, D=1024, H=16, HD=64, S=32, C=8. fp32.
// R16 = R15 + (a) attn_comb fused into outproj (5 stages/step),
//             (b) final_attn writes bf16 hi/lo operands directly (no cvt of O).

#define LL (size_t)

static const size_t OFF_QKVH = 0;                              // 8192*3072
static const size_t OFF_BUF  = OFF_QKVH + LL 8192 * 3072;      // 8*32*1024
static const size_t OFF_KVB  = OFF_BUF  + LL 8 * 32 * 1024;    // 8*32*2048
static const size_t OFF_CTX  = OFF_KVB  + LL 8 * 32 * 2048;
static const size_t OFF_TOK  = OFF_CTX + 8192;
static const size_t OFF_TMP  = OFF_TOK + 8192;
static const size_t OFF_TMP2 = OFF_TMP + 8192;
static const size_t OFF_H1   = OFF_TMP2 + 8192;                // 8*2048
static const size_t OFF_Q    = OFF_H1 + 16384;
static const size_t OFF_AO   = OFF_Q + 8192;
static const size_t OFF_KVS  = OFF_AO + 8192;                  // 64*2048
static const size_t OFF_SSUM = OFF_KVS + 131072;               // 64*1024
static const size_t OFF_PO   = OFF_SSUM + 65536;               // 8*16*4*64
static const size_t OFF_PMS  = OFF_PO + 32768;                 // 8*16*4*2
static const size_t OFF_PC   = OFF_PMS + 1024;                 // 8*8*1024
static const size_t OFF_ATT  = OFF_PC + 65536;                 // 8192*1024
static const size_t SCR_TOT  = OFF_ATT + LL 8192 * 1024;

__device__ __align__(16) float g_scratch[SCR_TOT];

// bf16 hi/lo pairs (pre-converted operands for the mma GEMMs)
static const size_t BHHI  = 0;                                 // hidden 8192*1024
static const size_t BHLO  = BHHI + LL 8388608;
static const size_t BWIHI = BHLO + LL 8388608;                 // attn_in_w 3072*1024
static const size_t BWILO = BWIHI + LL 3145728;
static const size_t BWOHI = BWILO + LL 3145728;                // attn_out_w 1024*1024
static const size_t BWOLO = BWOHI + LL 1048576;
static const size_t BOHI  = BWOLO + LL 1048576;                // O 8192*1024
static const size_t BOLO  = BOHI + LL 8388608;
static const size_t BF_TOT = BOLO + LL 8388608;

__device__ __align__(16) __nv_bfloat16 g_bf[BF_TOT];

__device__ __forceinline__ float geluf(float x) {
    return 0.5f * x * (1.0f + erff(x * 0.7071067811865475f));
}

__device__ __forceinline__ uint32_t smem_u32(const void* p) {
    uint32_t a;
    asm("{ .reg .u64 t; cvta.to.shared.u64 t, %1; cvt.u32.u64 %0, t; }"
        : "=r"(a) : "l"(p));
    return a;
}

__device__ __forceinline__ void ldsm_x4(uint32_t* r, uint32_t addr) {
    asm volatile("ldmatrix.sync.aligned.m8n8.x4.shared.b16 {%0,%1,%2,%3}, [%4];"
        : "=r"(r[0]), "=r"(r[1]), "=r"(r[2]), "=r"(r[3]) : "r"(addr));
}

__device__ __forceinline__ void mma16816(float* c, const uint32_t* a, const uint32_t* b) {
    asm volatile("mma.sync.aligned.m16n8k16.row.col.f32.bf16.bf16.f32 "
        "{%0,%1,%2,%3}, {%4,%5,%6,%7}, {%8,%9}, {%0,%1,%2,%3};"
        : "+f"(c[0]), "+f"(c[1]), "+f"(c[2]), "+f"(c[3])
        : "r"(a[0]), "r"(a[1]), "r"(a[2]), "r"(a[3]), "r"(b[0]), "r"(b[1]));
}

// x -> (hi, lo) bf16 pair, 4 floats per thread.
__global__ void cvt_pair(const float* __restrict__ x, __nv_bfloat16* __restrict__ hi,
                         __nv_bfloat16* __restrict__ lo, int n4) {
    int i = blockIdx.x * 256 + threadIdx.x;
    if (i >= n4) return;
    float4 v = reinterpret_cast<const float4*>(x)[i];
    float f[4] = {v.x, v.y, v.z, v.w};
    uint32_t hs[4], ls[4];
    #pragma unroll
    for (int j = 0; j < 4; ++j) {
        __nv_bfloat16 h = __float2bfloat16_rn(f[j]);
        hs[j] = (uint32_t)__bfloat16_as_ushort(h);
        ls[j] = (uint32_t)__bfloat16_as_ushort(
            __float2bfloat16_rn(f[j] - __bfloat162float(h)));
    }
    uint2 hv, lv;
    hv.x = hs[0] | (hs[1] << 16); hv.y = hs[2] | (hs[3] << 16);
    lv.x = ls[0] | (ls[1] << 16); lv.y = ls[2] | (ls[3] << 16);
    reinterpret_cast<uint2*>(hi)[i] = hv;
    reinterpret_cast<uint2*>(lo)[i] = lv;
}

// ============================================================================
// mmagemm: C[128·by+:128, 64·bx+:64] = A@B^T + bias, fp32 via bf16 hi/lo split.
// ============================================================================
__global__ __launch_bounds__(256) void mmagemm(
    const __nv_bfloat16* __restrict__ Ahi, const __nv_bfloat16* __restrict__ Alo,
    const __nv_bfloat16* __restrict__ Bhi, const __nv_bfloat16* __restrict__ Blo,
    const float* __restrict__ bias, float* __restrict__ C, int N, int K)
{
    __shared__ __align__(16) __nv_bfloat16 sAh[128][40];
    __shared__ __align__(16) __nv_bfloat16 sAl[128][40];
    __shared__ __align__(16) __nv_bfloat16 sBh[64][40];
    __shared__ __align__(16) __nv_bfloat16 sBl[64][40];
    int tid = threadIdx.x, lane = tid & 31, wid = tid >> 5;
    int bm = blockIdx.y * 128, bn = blockIdx.x * 64;
    int wm = (wid & 3) * 32, wn = (wid >> 2) * 32;

    float acc[2][4][4];
    #pragma unroll
    for (int mi = 0; mi < 2; ++mi)
        #pragma unroll
        for (int ni = 0; ni < 4; ++ni)
            #pragma unroll
            for (int j = 0; j < 4; ++j) acc[mi][ni][j] = 0.f;

    uint32_t sAh0 = smem_u32(sAh), sAl0 = smem_u32(sAl);
    uint32_t sBh0 = smem_u32(sBh), sBl0 = smem_u32(sBl);
    uint32_t aoff0 = ((wm + (lane & 15)) * 40 + ((lane & 16) >> 1)) * 2;
    uint32_t aoff1 = aoff0 + 16 * 40 * 2;
    uint32_t boff0 = ((wn + (lane & 7) + ((lane & 16) >> 1)) * 40 + ((lane & 8) ? 8 : 0)) * 2;
    uint32_t boff1 = boff0 + 16 * 40 * 2;

    for (int kk = 0; kk < K; kk += 32) {
        for (int c = tid; c < 512; c += 256) {
            int r = c >> 2, cg = (c & 3) << 3;
            *reinterpret_cast<uint4*>(&sAh[r][cg]) =
                *reinterpret_cast<const uint4*>(Ahi + LL(bm + r) * K + kk + cg);
            *reinterpret_cast<uint4*>(&sAl[r][cg]) =
                *reinterpret_cast<const uint4*>(Alo + LL(bm + r) * K + kk + cg);
        }
        {
            int r = tid >> 2, cg = (tid & 3) << 3;
            *reinterpret_cast<uint4*>(&sBh[r][cg]) =
                *reinterpret_cast<const uint4*>(Bhi + LL(bn + r) * K + kk + cg);
            *reinterpret_cast<uint4*>(&sBl[r][cg]) =
                *reinterpret_cast<const uint4*>(Blo + LL(bn + r) * K + kk + cg);
        }
        __syncthreads();
        #pragma unroll
        for (int k16 = 0; k16 < 2; ++k16) {
            uint32_t kb = (uint32_t)(k16 * 32);
            uint32_t ah[2][4], al[2][4], bh[4][2], bl[4][2], t[4];
            ldsm_x4(ah[0], sAh0 + aoff0 + kb);
            ldsm_x4(ah[1], sAh0 + aoff1 + kb);
            ldsm_x4(al[0], sAl0 + aoff0 + kb);
            ldsm_x4(al[1], sAl0 + aoff1 + kb);
            ldsm_x4(t, sBh0 + boff0 + kb);
            bh[0][0] = t[0]; bh[0][1] = t[1]; bh[1][0] = t[2]; bh[1][1] = t[3];
            ldsm_x4(t, sBh0 + boff1 + kb);
            bh[2][0] = t[0]; bh[2][1] = t[1]; bh[3][0] = t[2]; bh[3][1] = t[3];
            ldsm_x4(t, sBl0 + boff0 + kb);
            bl[0][0] = t[0]; bl[0][1] = t[1]; bl[1][0] = t[2]; bl[1][1] = t[3];
            ldsm_x4(t, sBl0 + boff1 + kb);
            bl[2][0] = t[0]; bl[2][1] = t[1]; bl[3][0] = t[2]; bl[3][1] = t[3];
            #pragma unroll
            for (int mi = 0; mi < 2; ++mi)
                #pragma unroll
                for (int ni = 0; ni < 4; ++ni) {
                    mma16816(acc[mi][ni], ah[mi], bh[ni]);
                    mma16816(acc[mi][ni], ah[mi], bl[ni]);
                    mma16816(acc[mi][ni], al[mi], bh[ni]);
                }
        }
        __syncthreads();
    }

    int g = lane >> 2, tq = lane & 3;
    #pragma unroll
    for (int mi = 0; mi < 2; ++mi)
        #pragma unroll
        for (int ni = 0; ni < 4; ++ni) {
            int row0 = bm + wm + mi * 16 + g;
            int col = bn + wn + ni * 8 + tq * 2;
            float b0 = bias[col], b1 = bias[col + 1];
            C[LL row0 * N + col]           = acc[mi][ni][0] + b0;
            C[LL row0 * N + col + 1]       = acc[mi][ni][1] + b1;
            C[LL(row0 + 8) * N + col]      = acc[mi][ni][2] + b0;
            C[LL(row0 + 8) * N + col + 1]  = acc[mi][ni][3] + b1;
        }
}

// ============================== misc kernels ================================

__global__ void mean_part(const float* __restrict__ hidden, float* __restrict__ pc) {
    int d = blockIdx.x * 256 + threadIdx.x;
    int b = blockIdx.y, z = blockIdx.z;
    const float* p = hidden + LL b * 1048576 + LL z * 131072 + d;
    float s = 0.f;
    #pragma unroll 8
    for (int l = 0; l < 128; ++l) s += p[LL l * 1024];
    pc[(z * 8 + b) * 1024 + d] = s;
}

__global__ void mean_comb(const float* __restrict__ pc, float* __restrict__ ctx) {
    int i = blockIdx.x * 256 + threadIdx.x;
    int b = i >> 10, d = i & 1023;
    float s = 0.f;
    #pragma unroll
    for (int z = 0; z < 8; ++z) s += pc[(z * 8 + b) * 1024 + d];
    ctx[i] = s * (1.0f / 1024.0f);
}

__global__ void copy_to_buf(const float* __restrict__ tok, float* __restrict__ buf, int slot) {
    int b = blockIdx.x;
    int d = blockIdx.y * 256 + threadIdx.x;
    buf[LL(b * 32 + slot) * 1024 + d] = tok[b * 1024 + d];
}

// Scalar GEMM (small phase-C GEMMs only).
__global__ __launch_bounds__(256) void sgemm(
    const float* __restrict__ A, const float* __restrict__ B,
    const float* __restrict__ bias, float* __restrict__ C,
    int M, int N, int K)
{
    __shared__ __align__(16) float As[16][128];
    __shared__ __align__(16) float Bs[16][64];
    int tid = threadIdx.x;
    int tx = tid & 15, ty = tid >> 4;
    int bm = blockIdx.y * 128, bn = blockIdx.x * 64;
    float acc[8][4];
    #pragma unroll
    for (int i = 0; i < 8; ++i)
        #pragma unroll
        for (int j = 0; j < 4; ++j) acc[i][j] = 0.f;

    for (int kk = 0; kk < K; kk += 16) {
        #pragma unroll
        for (int s = tid; s < 512; s += 256) {
            int r = s >> 2, c = (s & 3) << 2;
            int gr = bm + r;
            float4 v = make_float4(0.f, 0.f, 0.f, 0.f);
            if (gr < M) v = *reinterpret_cast<const float4*>(A + LL gr * K + kk + c);
            As[c][r] = v.x; As[c + 1][r] = v.y; As[c + 2][r] = v.z; As[c + 3][r] = v.w;
        }
        {
            int r = tid >> 2, c = (tid & 3) << 2;
            float4 v = *reinterpret_cast<const float4*>(B + LL(bn + r) * K + kk + c);
            Bs[c][r] = v.x; Bs[c + 1][r] = v.y; Bs[c + 2][r] = v.z; Bs[c + 3][r] = v.w;
        }
        __syncthreads();
        #pragma unroll
        for (int k = 0; k < 16; ++k) {
            float a[8], bb[4];
            #pragma unroll
            for (int i = 0; i < 8; ++i) a[i] = As[k][ty * 8 + i];
            #pragma unroll
            for (int j = 0; j < 4; ++j) bb[j] = Bs[k][tx * 4 + j];
            #pragma unroll
            for (int i = 0; i < 8; ++i)
                #pragma unroll
                for (int j = 0; j < 4; ++j) acc[i][j] += a[i] * bb[j];
        }
        __syncthreads();
    }
    #pragma unroll
    for (int i = 0; i < 8; ++i) {
        int row = bm + ty * 8 + i;
        if (row < M) {
            float* cr = C + LL row * N + bn + tx * 4;
            #pragma unroll
            for (int j = 0; j < 4; ++j) cr[j] = acc[i][j] + bias[bn + tx * 4 + j];
        }
    }
}

// out[b,n] = A[b,:K].W[n,:K] + bias[n], 8 rows, warp per n (Phase A tok0 only).
__global__ __launch_bounds__(256) void smallgemm8(
    const float* __restrict__ A, int K,
    const float* __restrict__ W, const float* __restrict__ bias,
    float* __restrict__ out, int N)
{
    __shared__ __align__(16) float As[8192];
    int tid = threadIdx.x, lane = tid & 31, w = tid >> 5;
    int n = blockIdx.x * 8 + w;
    float acc[8];
    #pragma unroll
    for (int b = 0; b < 8; ++b) acc[b] = 0.f;
    for (int kk = 0; kk < K; kk += 1024) {
        for (int i = tid; i < 8192; i += 256) {
            int b = i >> 10, k = i & 1023;
            As[i] = A[LL b * K + kk + k];
        }
        __syncthreads();
        const float4* wr = reinterpret_cast<const float4*>(W + LL n * K + kk);
        for (int k4 = lane; k4 < 256; k4 += 32) {
            float4 wv = wr[k4];
            #pragma unroll
            for (int b = 0; b < 8; ++b) {
                float4 av = reinterpret_cast<const float4*>(As + b * 1024)[k4];
                acc[b] += wv.x * av.x + wv.y * av.y + wv.z * av.z + wv.w * av.w;
            }
        }
        __syncthreads();
    }
    #pragma unroll
    for (int off = 16; off; off >>= 1)
        #pragma unroll
        for (int b = 0; b < 8; ++b) acc[b] += __shfl_down_sync(0xffffffffu, acc[b], off);
    if (lane == 0) {
        float bv = bias[n];
        #pragma unroll
        for (int b = 0; b < 8; ++b) out[b * N + n] = acc[b] + bv;
    }
}

// In-place LayerNorm of 8 rows x 1024 staged in smem. blockDim == 256.
__device__ __forceinline__ void ln_inplace(float* sA, const float* g,
                                           const float* bv, float* st) {
    int tid = threadIdx.x, lane = tid & 31, w = tid >> 5;
    float s = 0.f;
    #pragma unroll
    for (int c = lane; c < 1024; c += 32) s += sA[w * 1024 + c];
    #pragma unroll
    for (int o = 16; o; o >>= 1) s += __shfl_xor_sync(0xffffffffu, s, o);
    float mean = s * (1.0f / 1024.0f);
    float v = 0.f;
    #pragma unroll
    for (int c = lane; c < 1024; c += 32) { float d = sA[w * 1024 + c] - mean; v += d * d; }
    #pragma unroll
    for (int o = 16; o; o >>= 1) v += __shfl_xor_sync(0xffffffffu, v, o);
    if (lane == 0) { st[w] = mean; st[8 + w] = rsqrtf(v * (1.0f / 1024.0f) + 1e-5f); }
    __syncthreads();
    for (int idx = tid; idx < 8192; idx += 256) {
        int r = idx >> 10, d = idx & 1023;
        sA[idx] = (sA[idx] - st[r]) * st[8 + r] * g[d] + bv[d];
    }
    __syncthreads();
}

// K0: (optional LN2 of pre) -> qkv. n<1024 -> q; else kvb slot step-1.
__global__ __launch_bounds__(256) void qkv_ln(
    const float* __restrict__ pre, float* tok,
    const float* __restrict__ aiw, const float* __restrict__ aib,
    const float* __restrict__ g2, const float* __restrict__ b2v,
    float* __restrict__ q, float* __restrict__ kvb, float* __restrict__ buf,
    int step, int do_ln)
{
    __shared__ __align__(16) float sA[8192];
    __shared__ float st[16];
    int tid = threadIdx.x, lane = tid & 31, w = tid >> 5;
    int bid = blockIdx.x;
    const float* src = do_ln ? pre : tok;
    for (int i = tid; i < 8192; i += 256) sA[i] = src[i];
    __syncthreads();
    if (do_ln) {
        ln_inplace(sA, g2, b2v, st);
        if (bid == 0) {
            for (int i = tid; i < 8192; i += 256) {
                tok[i] = sA[i];
                int b = i >> 10, d = i & 1023;
                buf[LL(b * 32 + step - 1) * 1024 + d] = sA[i];
            }
        }
    }
    int n = bid * 8 + w;
    const float4* wr = reinterpret_cast<const float4*>(aiw + LL n * 1024);
    float acc[8];
    #pragma unroll
    for (int b = 0; b < 8; ++b) acc[b] = 0.f;
    for (int k4 = lane; k4 < 256; k4 += 32) {
        float4 wv = wr[k4];
        #pragma unroll
        for (int b = 0; b < 8; ++b) {
            float4 av = reinterpret_cast<const float4*>(sA + b * 1024)[k4];
            acc[b] += wv.x * av.x + wv.y * av.y + wv.z * av.z + wv.w * av.w;
        }
    }
    #pragma unroll
    for (int off = 16; off; off >>= 1)
        #pragma unroll
        for (int b = 0; b < 8; ++b) acc[b] += __shfl_down_sync(0xffffffffu, acc[b], off);
    if (lane == 0) {
        float bv = aib[n];
        #pragma unroll
        for (int b = 0; b < 8; ++b) {
            float v = acc[b] + bv;
            if (n < 1024) q[b * 1024 + n] = v;
            else kvb[LL(b * 32 + step - 1) * 2048 + (n - 1024)] = v;
        }
    }
}

// K1: split-K partial attention. 512 blocks = (b, h, p) with p in [0,4).
__global__ __launch_bounds__(256) void attn_part(
    const float* __restrict__ q, const float* __restrict__ qkvh,
    const float* __restrict__ kvb, float* __restrict__ po,
    float* __restrict__ pms, int Lk)
{
    int bid = blockIdx.x;
    int b = bid >> 6, h = (bid >> 2) & 15, p = bid & 3;
    int chunk = (Lk + 3) >> 2;
    int j0 = p * chunk;
    int j1 = j0 + chunk; if (j1 > Lk) j1 = Lk;
    int cnt = j1 - j0;
    __shared__ __align__(16) float sq[64];
    __shared__ float sc[272];
    __shared__ float red[256];
    __shared__ float part[8][64];
    int tid = threadIdx.x;
    if (tid < 64) sq[tid] = q[b * 1024 + h * 64 + tid];
    __syncthreads();

    float lmax = -1e30f;
    for (int jj = tid; jj < cnt; jj += 256) {
        int j = j0 + jj;
        const float* kr = (j < 1024)
            ? qkvh + LL(b * 1024 + j) * 3072 + 1024 + h * 64
            : kvb + LL(b * 32 + j - 1024) * 2048 + h * 64;
        const float4* k4 = reinterpret_cast<const float4*>(kr);
        const float4* q4 = reinterpret_cast<const float4*>(sq);
        float s = 0.f;
        #pragma unroll
        for (int d = 0; d < 16; ++d) {
            float4 kv = k4[d], qv = q4[d];
            s += kv.x * qv.x + kv.y * qv.y + kv.z * qv.z + kv.w * qv.w;
        }
        s *= 0.125f;
        sc[jj] = s;
        lmax = fmaxf(lmax, s);
    }
    red[tid] = lmax; __syncthreads();
    for (int o = 128; o; o >>= 1) { if (tid < o) red[tid] = fmaxf(red[tid], red[tid + o]); __syncthreads(); }
    float m = red[0];
    __syncthreads();
    float lsum = 0.f;
    for (int jj = tid; jj < cnt; jj += 256) { float e = __expf(sc[jj] - m); sc[jj] = e; lsum += e; }
    red[tid] = lsum; __syncthreads();
    for (int o = 128; o; o >>= 1) { if (tid < o) red[tid] += red[tid + o]; __syncthreads(); }
    float Ssum = red[0];

    int g = tid >> 5, d0 = (tid & 31) * 2;
    float ax = 0.f, ay = 0.f;
    for (int jj = g; jj < cnt; jj += 8) {
        int j = j0 + jj;
        const float* vr = (j < 1024)
            ? qkvh + LL(b * 1024 + j) * 3072 + 2048 + h * 64
            : kvb + LL(b * 32 + j - 1024) * 2048 + 1024 + h * 64;
        float2 v = *reinterpret_cast<const float2*>(vr + d0);
        float e = sc[jj];
        ax += e * v.x; ay += e * v.y;
    }
    part[g][d0] = ax; part[g][d0 + 1] = ay;
    __syncthreads();
    int idx = ((b * 16 + h) * 4 + p);
    if (tid < 64) {
        float s = 0.f;
        #pragma unroll
        for (int gg = 0; gg < 8; ++gg) s += part[gg][tid];
        po[idx * 64 + tid] = s;
    }
    if (tid == 0) { pms[idx * 2] = m; pms[idx * 2 + 1] = Ssum; }
}

// K2: fused combine + out-proj + residual. 128 blocks.
// Stage sA[idx] = combined attention out, then GEMV against aow.
__global__ __launch_bounds__(256) void outproj_comb_res(
    const float* __restrict__ po, const float* __restrict__ pms,
    const float* __restrict__ aow, const float* __restrict__ aob,
    const float* __restrict__ tok, float* __restrict__ tmp)
{
    __shared__ __align__(16) float sA[8192];
    __shared__ float wcs[512];   // per (bh,p): exp(m_p - M) / S_total
    int tid = threadIdx.x, lane = tid & 31, w = tid >> 5;
    if (tid < 128) {
        int bh = tid;
        float ms[4], ss[4];
        float M = -1e30f;
        #pragma unroll
        for (int p = 0; p < 4; ++p) {
            ms[p] = pms[(bh * 4 + p) * 2];
            ss[p] = pms[(bh * 4 + p) * 2 + 1];
            M = fmaxf(M, ms[p]);
        }
        float S = 0.f;
        float wv[4];
        #pragma unroll
        for (int p = 0; p < 4; ++p) { wv[p] = __expf(ms[p] - M); S += ss[p] * wv[p]; }
        float inv = 1.0f / S;
        #pragma unroll
        for (int p = 0; p < 4; ++p) wcs[bh * 4 + p] = wv[p] * inv;
    }
    __syncthreads();
    for (int idx = tid; idx < 8192; idx += 256) {
        int bh = idx >> 6, d = idx & 63;
        float s = 0.f;
        #pragma unroll
        for (int p = 0; p < 4; ++p)
            s += po[(bh * 4 + p) * 64 + d] * wcs[bh * 4 + p];
        sA[idx] = s;
    }
    __syncthreads();
    int n = blockIdx.x * 8 + w;
    const float4* wr = reinterpret_cast<const float4*>(aow + LL n * 1024);
    float acc[8];
    #pragma unroll
    for (int b = 0; b < 8; ++b) acc[b] = 0.f;
    for (int k4 = lane; k4 < 256; k4 += 32) {
        float4 wv = wr[k4];
        #pragma unroll
        for (int b = 0; b < 8; ++b) {
            float4 av = reinterpret_cast<const float4*>(sA + b * 1024)[k4];
            acc[b] += wv.x * av.x + wv.y * av.y + wv.z * av.z + wv.w * av.w;
        }
    }
    #pragma unroll
    for (int off = 16; off; off >>= 1)
        #pragma unroll
        for (int b = 0; b < 8; ++b) acc[b] += __shfl_down_sync(0xffffffffu, acc[b], off);
    if (lane == 0) {
        float bv = aob[n];
        #pragma unroll
        for (int b = 0; b < 8; ++b)
            tmp[b * 1024 + n] = acc[b] + bv + tok[b * 1024 + n];
    }
}

// K3: LN1(tmp) in-block -> FFN1 + gelu -> h1. bid 0 publishes tokl.
__global__ __launch_bounds__(256) void ffn1_ln(
    const float* __restrict__ tmp,
    const float* __restrict__ g1, const float* __restrict__ b1v,
    const float* __restrict__ fw1, const float* __restrict__ fb1,
    float* __restrict__ h1, float* __restrict__ tokl)
{
    __shared__ __align__(16) float sA[8192];
    __shared__ float st[16];
    int tid = threadIdx.x, lane = tid & 31, w = tid >> 5;
    int bid = blockIdx.x;
    for (int i = tid; i < 8192; i += 256) sA[i] = tmp[i];
    __syncthreads();
    ln_inplace(sA, g1, b1v, st);
    if (bid == 0)
        for (int i = tid; i < 8192; i += 256) tokl[i] = sA[i];
    int n = bid * 8 + w;
    const float4* wr = reinterpret_cast<const float4*>(fw1 + LL n * 1024);
    float acc[8];
    #pragma unroll
    for (int b = 0; b < 8; ++b) acc[b] = 0.f;
    for (int k4 = lane; k4 < 256; k4 += 32) {
        float4 wv = wr[k4];
        #pragma unroll
        for (int b = 0; b < 8; ++b) {
            float4 av = reinterpret_cast<const float4*>(sA + b * 1024)[k4];
            acc[b] += wv.x * av.x + wv.y * av.y + wv.z * av.z + wv.w * av.w;
        }
    }
    #pragma unroll
    for (int off = 16; off; off >>= 1)
        #pragma unroll
        for (int b = 0; b < 8; ++b) acc[b] += __shfl_down_sync(0xffffffffu, acc[b], off);
    if (lane == 0) {
        float bv = fb1[n];
        #pragma unroll
        for (int b = 0; b < 8; ++b) h1[b * 2048 + n] = geluf(acc[b] + bv);
    }
}

// K4: tmp2 = h1 @ fw2^T + fb2 + tokl (residual). 128 blocks.
__global__ __launch_bounds__(256) void ffn2_res(
    const float* __restrict__ h1, const float* __restrict__ fw2,
    const float* __restrict__ fb2, const float* __restrict__ tokl,
    float* __restrict__ tmp2)
{
    __shared__ __align__(16) float sA[8192];
    int tid = threadIdx.x, lane = tid & 31, w = tid >> 5;
    int n = blockIdx.x * 8 + w;
    float acc[8];
    #pragma unroll
    for (int b = 0; b < 8; ++b) acc[b] = 0.f;
    for (int kk = 0; kk < 2048; kk += 1024) {
        for (int i = tid; i < 8192; i += 256) {
            int b = i >> 10, k = i & 1023;
            sA[i] = h1[b * 2048 + kk + k];
        }
        __syncthreads();
        const float4* wr = reinterpret_cast<const float4*>(fw2 + LL n * 2048 + kk);
        for (int k4 = lane; k4 < 256; k4 += 32) {
            float4 wv = wr[k4];
            #pragma unroll
            for (int b = 0; b < 8; ++b) {
                float4 av = reinterpret_cast<const float4*>(sA + b * 1024)[k4];
                acc[b] += wv.x * av.x + wv.y * av.y + wv.z * av.z + wv.w * av.w;
            }
        }
        __syncthreads();
    }
    #pragma unroll
    for (int off = 16; off; off >>= 1)
        #pragma unroll
        for (int b = 0; b < 8; ++b) acc[b] += __shfl_down_sync(0xffffffffu, acc[b], off);
    if (lane == 0) {
        float bv = fb2[n];
        #pragma unroll
        for (int b = 0; b < 8; ++b)
            tmp2[b * 1024 + n] = acc[b] + bv + tokl[b * 1024 + n];
    }
}

__global__ void ln8(const float* __restrict__ x, const float* __restrict__ gg,
                    const float* __restrict__ bb, float* __restrict__ out,
                    float* __restrict__ buf, int slot)
{
    int b = blockIdx.x, tid = threadIdx.x;
    __shared__ float red[256];
    const float* xr = x + b * 1024;
    float vals[4]; float s = 0.f;
    #pragma unroll
    for (int i = 0; i < 4; ++i) { vals[i] = xr[tid + 256 * i]; s += vals[i]; }
    red[tid] = s; __syncthreads();
    for (int o = 128; o; o >>= 1) { if (tid < o) red[tid] += red[tid + o]; __syncthreads(); }
    float mean = red[0] * (1.0f / 1024.0f);
    __syncthreads();
    float v = 0.f;
    #pragma unroll
    for (int i = 0; i < 4; ++i) { float dd = vals[i] - mean; v += dd * dd; }
    red[tid] = v; __syncthreads();
    for (int o = 128; o; o >>= 1) { if (tid < o) red[tid] += red[tid + o]; __syncthreads(); }
    float inv = rsqrtf(red[0] * (1.0f / 1024.0f) + 1e-5f);
    #pragma unroll
    for (int i = 0; i < 4; ++i) {
        int d = tid + 256 * i;
        float y = (vals[i] - mean) * inv * gg[d] + bb[d];
        out[b * 1024 + d] = y;
        if (buf) buf[LL(b * 32 + slot) * 1024 + d] = y;
    }
}

__global__ void ln_big(const float* __restrict__ hidden, const float* __restrict__ att,
                       const float* __restrict__ gg, const float* __restrict__ bb,
                       float* __restrict__ out)
{
    int l = blockIdx.x, tid = threadIdx.x;
    __shared__ float red[256];
    const float* hr = hidden + LL l * 1024;
    const float* ar = att + LL l * 1024;
    float vals[4]; float s = 0.f;
    #pragma unroll
    for (int i = 0; i < 4; ++i) { vals[i] = hr[tid + 256 * i] + ar[tid + 256 * i]; s += vals[i]; }
    red[tid] = s; __syncthreads();
    for (int o = 128; o; o >>= 1) { if (tid < o) red[tid] += red[tid + o]; __syncthreads(); }
    float mean = red[0] * (1.0f / 1024.0f);
    __syncthreads();
    float v = 0.f;
    #pragma unroll
    for (int i = 0; i < 4; ++i) { float dd = vals[i] - mean; v += dd * dd; }
    red[tid] = v; __syncthreads();
    for (int o = 128; o; o >>= 1) { if (tid < o) red[tid] += red[tid + o]; __syncthreads(); }
    float inv = rsqrtf(red[0] * (1.0f / 1024.0f) + 1e-5f);
    #pragma unroll
    for (int i = 0; i < 4; ++i) {
        int d = tid + 256 * i;
        out[LL l * 1024 + d] = (vals[i] - mean) * inv * gg[d] + bb[d];
    }
}

__global__ __launch_bounds__(256) void comp_kernel(
    const float* __restrict__ comp_q, const float* __restrict__ thoughts,
    float* __restrict__ ssum)
{
    int b = blockIdx.x >> 3, c = blockIdx.x & 7;
    __shared__ float sc[32];
    __shared__ float pr[32];
    int tid = threadIdx.x, lane = tid & 31, w = tid >> 5;
    const float* qr = comp_q + c * 1024;
    #pragma unroll
    for (int si = 0; si < 4; ++si) {
        int s = w * 4 + si;
        const float* t = thoughts + LL(b * 32 + s) * 1024;
        float acc = 0.f;
        for (int k = lane; k < 1024; k += 32) acc += qr[k] * t[k];
        #pragma unroll
        for (int o = 16; o; o >>= 1) acc += __shfl_down_sync(0xffffffffu, acc, o);
        if (lane == 0) sc[s] = acc * (1.0f / 32.0f);
    }
    __syncthreads();
    if (tid == 0) {
        float m = -1e30f;
        for (int s = 0; s < 32; ++s) m = fmaxf(m, sc[s]);
        float S = 0.f;
        for (int s = 0; s < 32; ++s) { float p = __expf(sc[s] - m); pr[s] = p; S += p; }
        float iv = 1.0f / S;
        for (int s = 0; s < 32; ++s) pr[s] *= iv;
    }
    __syncthreads();
    for (int d = tid; d < 1024; d += 256) {
        float acc = 0.f;
        #pragma unroll
        for (int s = 0; s < 32; ++s) acc += pr[s] * thoughts[LL(b * 32 + s) * 1024 + d];
        ssum[LL(b * 8 + c) * 1024 + d] = acc;
    }
}

// Final MHA; writes attention output DIRECTLY as bf16 hi/lo mma operands.
__global__ __launch_bounds__(256) void final_attn(
    const float* __restrict__ qkvh, const float* __restrict__ kvs,
    __nv_bfloat16* __restrict__ ohi, __nv_bfloat16* __restrict__ olo)
{
    int tid = threadIdx.x, lane = tid & 31, w = tid >> 5;
    int pair = blockIdx.x * 8 + w;
    int l = pair >> 4, h = pair & 15;
    int b = l >> 10;
    float2 qv = reinterpret_cast<const float2*>(qkvh + LL l * 3072 + h * 64)[lane];
    float s[8];
    #pragma unroll
    for (int ks = 0; ks < 8; ++ks) {
        float2 kv = reinterpret_cast<const float2*>(kvs + LL(b * 8 + ks) * 2048 + h * 64)[lane];
        float p = qv.x * kv.x + qv.y * kv.y;
        #pragma unroll
        for (int off = 16; off; off >>= 1) p += __shfl_xor_sync(0xffffffffu, p, off);
        s[ks] = p * 0.125f;
    }
    float m = s[0];
    #pragma unroll
    for (int ks = 1; ks < 8; ++ks) m = fmaxf(m, s[ks]);
    float sum = 0.f;
    #pragma unroll
    for (int ks = 0; ks < 8; ++ks) { s[ks] = __expf(s[ks] - m); sum += s[ks]; }
    float inv = 1.0f / sum;
    float o0 = 0.f, o1 = 0.f;
    #pragma unroll
    for (int ks = 0; ks < 8; ++ks) {
        float2 vv = reinterpret_cast<const float2*>(kvs + LL(b * 8 + ks) * 2048 + 1024 + h * 64)[lane];
        o0 += s[ks] * vv.x; o1 += s[ks] * vv.y;
    }
    o0 *= inv; o1 *= inv;
    // convert to bf16 hi/lo pairs, packed store (2 elems per lane)
    __nv_bfloat16 h0 = __float2bfloat16_rn(o0);
    __nv_bfloat16 h1 = __float2bfloat16_rn(o1);
    uint32_t hp = (uint32_t)__bfloat16_as_ushort(h0) |
                  ((uint32_t)__bfloat16_as_ushort(h1) << 16);
    uint32_t lp = (uint32_t)__bfloat16_as_ushort(
                      __float2bfloat16_rn(o0 - __bfloat162float(h0))) |
                  ((uint32_t)__bfloat16_as_ushort(
                      __float2bfloat16_rn(o1 - __bfloat162float(h1))) << 16);
    size_t widx = LL l * 512 + h * 32 + lane;
    reinterpret_cast<uint32_t*>(ohi)[widx] = hp;
    reinterpret_cast<uint32_t*>(olo)[widx] = lp;
}

extern "C" void kernel_launch(void* const* d_in, const int* in_sizes, int n_in,
                              void* d_out, int out_size) {
    (void)in_sizes; (void)n_in; (void)out_size;
    const float* hidden = (const float*)d_in[0];
    const float* tpw    = (const float*)d_in[1];
    const float* tpb    = (const float*)d_in[2];
    const float* ln1g   = (const float*)d_in[3];
    const float* ln1b   = (const float*)d_in[4];
    const float* ln2g   = (const float*)d_in[5];
    const float* ln2b   = (const float*)d_in[6];
    const float* aiw    = (const float*)d_in[7];
    const float* aib    = (const float*)d_in[8];
    const float* aow    = (const float*)d_in[9];
    const float* aob    = (const float*)d_in[10];
    const float* fw1    = (const float*)d_in[11];
    const float* fb1    = (const float*)d_in[12];
    const float* fw2    = (const float*)d_in[13];
    const float* fb2    = (const float*)d_in[14];
    const float* cq     = (const float*)d_in[15];
    const float* cw     = (const float*)d_in[16];
    const float* cb     = (const float*)d_in[17];
    float* out = (float*)d_out;

    float* S;
    cudaGetSymbolAddress((void**)&S, g_scratch);
    __nv_bfloat16* BF;
    cudaGetSymbolAddress((void**)&BF, g_bf);

    float* QKVH = S + OFF_QKVH;
    float* BUF  = S + OFF_BUF;
    float* KVB  = S + OFF_KVB;
    float* CTX  = S + OFF_CTX;
    float* TOK  = S + OFF_TOK;
    float* TMP  = S + OFF_TMP;
    float* TMP2 = S + OFF_TMP2;
    float* H1   = S + OFF_H1;
    float* Q    = S + OFF_Q;
    float* KVS  = S + OFF_KVS;
    float* SSUM = S + OFF_SSUM;
    float* PO   = S + OFF_PO;
    float* PMS  = S + OFF_PMS;
    float* PC   = S + OFF_PC;
    float* ATT  = S + OFF_ATT;
    float* SUMM = out + LL 8192 * 1024;   // (8,8,1024) tail of output
    float* TOKL = CTX;                    // ctx is dead after tok0

    // Phase A: operand conversion + two-phase mean + tensor-core QKV.
    cvt_pair<<<8192, 256>>>(hidden, BF + BHHI, BF + BHLO, 2097152);
    cvt_pair<<<3072, 256>>>(aiw, BF + BWIHI, BF + BWILO, 786432);
    cvt_pair<<<1024, 256>>>(aow, BF + BWOHI, BF + BWOLO, 262144);
    mean_part<<<dim3(4, 8, 8), 256>>>(hidden, PC);
    mean_comb<<<32, 256>>>(PC, CTX);
    smallgemm8<<<128, 256>>>(CTX, 1024, tpw, tpb, TOK, 1024);
    copy_to_buf<<<dim3(8, 4), 256>>>(TOK, BUF, 0);
    mmagemm<<<dim3(48, 64), 256>>>(BF + BHHI, BF + BHLO, BF + BWIHI, BF + BWILO,
                                   aib, QKVH, 3072, 1024);

    // Phase B: 31 steps x 5 kernels (combine fused into outproj)
    for (int i = 1; i < 32; ++i) {
        qkv_ln<<<384, 256>>>(TMP2, TOK, aiw, aib, ln2g, ln2b, Q, KVB, BUF, i, i > 1);
        attn_part<<<512, 256>>>(Q, QKVH, KVB, PO, PMS, 1024 + i);
        outproj_comb_res<<<128, 256>>>(PO, PMS, aow, aob, TOK, TMP);
        ffn1_ln<<<256, 256>>>(TMP, ln1g, ln1b, fw1, fb1, H1, TOKL);
        ffn2_res<<<128, 256>>>(H1, fw2, fb2, TOKL, TMP2);
    }
    ln8<<<8, 256>>>(TMP2, ln2g, ln2b, TOK, BUF, 31);

    // Phase C
    comp_kernel<<<64, 256>>>(cq, BUF, SSUM);
    sgemm<<<dim3(16, 1), 256>>>(SSUM, cw, cb, SUMM, 64, 1024, 1024);
    sgemm<<<dim3(32, 1), 256>>>(SUMM, aiw + LL 1024 * 1024, aib + 1024, KVS, 64, 2048, 1024);
    final_attn<<<16384, 256>>>(QKVH, KVS, BF + BOHI, BF + BOLO);
    mmagemm<<<dim3(16, 64), 256>>>(BF + BOHI, BF + BOLO, BF + BWOHI, BF + BWOLO,
                                   aob, ATT, 1024, 1024);
    ln_big<<<8192, 256>>>(hidden, ATT, ln1g, ln1b, out);
}